// round 1
// baseline (speedup 1.0000x reference)
#include <cuda_runtime.h>
#include <cstddef>

// Problem constants
#define NB   4
#define TLEN 2048
#define DMODEL 1024
#define NH   16
#define DK   64
#define MROWS (NB * TLEN)        // 8192
#define QKVCOLS (3 * DMODEL)     // 3072

// Scratch (device globals: allocation-free per harness rules)
__device__ float g_qkv[(size_t)MROWS * QKVCOLS];  // 100.7 MB
__device__ float g_att[(size_t)MROWS * DMODEL];   // 33.6 MB

// ---------------------------------------------------------------------------
// SGEMM: C[M,N] = A[M,K] * B[K,N], all row-major. BM=BN=128, BK=8, 8x8/thread.
// ---------------------------------------------------------------------------
__global__ __launch_bounds__(256)
void sgemm128_kernel(const float* __restrict__ A, const float* __restrict__ B,
                     float* __restrict__ C, int M, int N, int K)
{
    constexpr int BM = 128, BN = 128, BK = 8, TM = 8, TN = 8;
    __shared__ float As[BK][BM];
    __shared__ float Bs[BK][BN];

    const int tid = threadIdx.x;
    const int tx = tid & 15;        // 0..15 -> N direction
    const int ty = tid >> 4;        // 0..15 -> M direction
    const int row0 = blockIdx.y * BM;
    const int col0 = blockIdx.x * BN;

    // A loader: 128x8 tile, 4 floats/thread
    const int aRow = tid >> 1;                 // 0..127
    const int aCol = (tid & 1) << 2;           // 0 or 4
    // B loader: 8x128 tile, 4 floats/thread
    const int bRow = tid >> 5;                 // 0..7
    const int bCol = (tid & 31) << 2;          // 0..124

    const float* Ab = A + (size_t)(row0 + aRow) * K + aCol;
    const float* Bb = B + (size_t)bRow * N + col0 + bCol;

    float acc[TM][TN];
#pragma unroll
    for (int i = 0; i < TM; i++)
#pragma unroll
        for (int j = 0; j < TN; j++) acc[i][j] = 0.0f;

    for (int k0 = 0; k0 < K; k0 += BK) {
        float4 a4 = *reinterpret_cast<const float4*>(Ab + k0);
        As[aCol + 0][aRow] = a4.x;
        As[aCol + 1][aRow] = a4.y;
        As[aCol + 2][aRow] = a4.z;
        As[aCol + 3][aRow] = a4.w;
        float4 b4 = *reinterpret_cast<const float4*>(Bb + (size_t)k0 * N);
        *reinterpret_cast<float4*>(&Bs[bRow][bCol]) = b4;
        __syncthreads();

#pragma unroll
        for (int kk = 0; kk < BK; kk++) {
            float ar[TM], br[TN];
#pragma unroll
            for (int i = 0; i < TM; i++) ar[i] = As[kk][(ty << 3) + i];
#pragma unroll
            for (int j = 0; j < TN; j++) br[j] = Bs[kk][(tx << 3) + j];
#pragma unroll
            for (int i = 0; i < TM; i++)
#pragma unroll
                for (int j = 0; j < TN; j++)
                    acc[i][j] = fmaf(ar[i], br[j], acc[i][j]);
        }
        __syncthreads();
    }

#pragma unroll
    for (int i = 0; i < TM; i++) {
        float* Crow = C + (size_t)(row0 + (ty << 3) + i) * N + col0 + (tx << 3);
#pragma unroll
        for (int j = 0; j < TN; j += 4) {
            float4 v = make_float4(acc[i][j], acc[i][j + 1], acc[i][j + 2], acc[i][j + 3]);
            *reinterpret_cast<float4*>(Crow + j) = v;
        }
    }
}

// ---------------------------------------------------------------------------
// Flash attention (causal), fp32. One CTA per (q-tile of 64, head, batch).
// Smem: Qt (transposed), Kt (transposed, reused as P), Vs (natural) = 48 KB.
// Thread grid 16x16; each thread owns a 4x4 tile of S / O.
// ---------------------------------------------------------------------------
__global__ __launch_bounds__(256)
void flash_attn_kernel(const float* __restrict__ qkv, float* __restrict__ attout)
{
    const int qt = blockIdx.x;   // 0..31
    const int h  = blockIdx.y;   // 0..15
    const int n  = blockIdx.z;   // 0..3
    const int tid = threadIdx.x;
    const int tx = tid & 15;
    const int ty = tid >> 4;

    __shared__ float Qt[64][64];   // Qt[d][q]
    __shared__ float Kt[64][64];   // Kt[d][k]; reused as P[q][k]
    __shared__ float Vs[64][64];   // Vs[k][d]

    // tile loader mapping: 4 float4 per thread
    const int lr = tid >> 2;              // 0..63
    const int lc = (tid & 3) << 4;        // 0,16,32,48

    const size_t rs = QKVCOLS;
    const float* qbase = qkv + ((size_t)(n * TLEN + qt * 64)) * rs + h * DK;

    // Load Q tile transposed: Qt[d][r]
#pragma unroll
    for (int u = 0; u < 16; u += 4) {
        float4 v = *reinterpret_cast<const float4*>(qbase + (size_t)lr * rs + lc + u);
        Qt[lc + u + 0][lr] = v.x;
        Qt[lc + u + 1][lr] = v.y;
        Qt[lc + u + 2][lr] = v.z;
        Qt[lc + u + 3][lr] = v.w;
    }

    float m[4], l[4], o[4][4];
#pragma unroll
    for (int i = 0; i < 4; i++) {
        m[i] = -1e30f; l[i] = 0.0f;
#pragma unroll
        for (int j = 0; j < 4; j++) o[i][j] = 0.0f;
    }

    const float scale = 0.125f; // 1/sqrt(64)

    for (int kt = 0; kt <= qt; kt++) {
        __syncthreads();  // previous iter done with Kt(P)/Vs; Q ready on iter 0

        const float* kbase = qkv + ((size_t)(n * TLEN + kt * 64)) * rs + DMODEL + h * DK;
        const float* vbase = kbase + DMODEL;
#pragma unroll
        for (int u = 0; u < 16; u += 4) {
            float4 v = *reinterpret_cast<const float4*>(kbase + (size_t)lr * rs + lc + u);
            Kt[lc + u + 0][lr] = v.x;
            Kt[lc + u + 1][lr] = v.y;
            Kt[lc + u + 2][lr] = v.z;
            Kt[lc + u + 3][lr] = v.w;
            float4 w = *reinterpret_cast<const float4*>(vbase + (size_t)lr * rs + lc + u);
            *reinterpret_cast<float4*>(&Vs[lr][lc + u]) = w;
        }
        __syncthreads();

        // S = Q K^T  (4x4 per thread)
        float s[4][4];
#pragma unroll
        for (int i = 0; i < 4; i++)
#pragma unroll
            for (int j = 0; j < 4; j++) s[i][j] = 0.0f;

#pragma unroll 8
        for (int d = 0; d < 64; d++) {
            float4 qv = *reinterpret_cast<const float4*>(&Qt[d][ty << 2]);
            float4 kv = *reinterpret_cast<const float4*>(&Kt[d][tx << 2]);
            float qa[4] = {qv.x, qv.y, qv.z, qv.w};
            float ka[4] = {kv.x, kv.y, kv.z, kv.w};
#pragma unroll
            for (int i = 0; i < 4; i++)
#pragma unroll
                for (int j = 0; j < 4; j++)
                    s[i][j] = fmaf(qa[i], ka[j], s[i][j]);
        }

        const bool diag = (kt == qt);

        // online softmax per row
#pragma unroll
        for (int i = 0; i < 4; i++) {
            const int qrow = (ty << 2) + i;
            float rm = -1e30f;
#pragma unroll
            for (int j = 0; j < 4; j++) {
                float v = s[i][j] * scale;
                if (diag && ((tx << 2) + j > qrow)) v = -1e30f;
                s[i][j] = v;
                rm = fmaxf(rm, v);
            }
#pragma unroll
            for (int off = 8; off > 0; off >>= 1)
                rm = fmaxf(rm, __shfl_xor_sync(0xffffffffu, rm, off, 16));

            float mn = fmaxf(m[i], rm);
            float corr = __expf(m[i] - mn);
            float rsum = 0.0f;
#pragma unroll
            for (int j = 0; j < 4; j++) {
                float p = __expf(s[i][j] - mn);
                s[i][j] = p;
                rsum += p;
            }
#pragma unroll
            for (int off = 8; off > 0; off >>= 1)
                rsum += __shfl_xor_sync(0xffffffffu, rsum, off, 16);

            l[i] = l[i] * corr + rsum;
            m[i] = mn;
#pragma unroll
            for (int j = 0; j < 4; j++) o[i][j] *= corr;
        }

        __syncthreads();  // all threads done reading Kt for S

        // write P into Kt buffer, natural layout P[q][k], float4 stores
#pragma unroll
        for (int i = 0; i < 4; i++) {
            float4 pv = make_float4(s[i][0], s[i][1], s[i][2], s[i][3]);
            *reinterpret_cast<float4*>(&Kt[(ty << 2) + i][tx << 2]) = pv;
        }
        __syncthreads();

        // O += P @ V
#pragma unroll 8
        for (int kk = 0; kk < 64; kk++) {
            float4 vv = *reinterpret_cast<const float4*>(&Vs[kk][tx << 2]);
            float va[4] = {vv.x, vv.y, vv.z, vv.w};
            float pa[4];
#pragma unroll
            for (int i = 0; i < 4; i++) pa[i] = Kt[(ty << 2) + i][kk];
#pragma unroll
            for (int i = 0; i < 4; i++)
#pragma unroll
                for (int j = 0; j < 4; j++)
                    o[i][j] = fmaf(pa[i], va[j], o[i][j]);
        }
    }

    // epilogue: normalize and write [n, t, h*64 + d]
    float* obase = attout + ((size_t)(n * TLEN + qt * 64)) * DMODEL + h * DK;
#pragma unroll
    for (int i = 0; i < 4; i++) {
        float inv = 1.0f / l[i];
        float* orow = obase + (size_t)((ty << 2) + i) * DMODEL + (tx << 2);
        float4 v = make_float4(o[i][0] * inv, o[i][1] * inv, o[i][2] * inv, o[i][3] * inv);
        *reinterpret_cast<float4*>(orow) = v;
    }
}

// ---------------------------------------------------------------------------
// Launch
// ---------------------------------------------------------------------------
extern "C" void kernel_launch(void* const* d_in, const int* in_sizes, int n_in,
                              void* d_out, int out_size)
{
    const float* z    = (const float*)d_in[0];   // [4,2048,1024]
    const float* Wqkv = (const float*)d_in[1];   // [1024,3072]
    const float* Wout = (const float*)d_in[2];   // [1024,1024]
    float* out = (float*)d_out;                  // [4,2048,1024]

    void* pqkv = nullptr;
    void* patt = nullptr;
    cudaGetSymbolAddress(&pqkv, g_qkv);
    cudaGetSymbolAddress(&patt, g_att);
    float* qkv = (float*)pqkv;
    float* att = (float*)patt;

    // 1) qkv = z @ Wqkv   (8192x1024 @ 1024x3072)
    {
        dim3 grid(QKVCOLS / 128, MROWS / 128);
        sgemm128_kernel<<<grid, 256>>>(z, Wqkv, qkv, MROWS, QKVCOLS, DMODEL);
    }

    // 2) causal flash attention per (q-tile, head, batch)
    {
        dim3 grid(TLEN / 64, NH, NB);
        flash_attn_kernel<<<grid, 256>>>(qkv, att);
    }

    // 3) out = att @ Wout  (8192x1024 @ 1024x1024)
    {
        dim3 grid(DMODEL / 128, MROWS / 128);
        sgemm128_kernel<<<grid, 256>>>(att, Wout, out, MROWS, DMODEL, DMODEL);
    }
}

// round 3
// speedup vs baseline: 1.7774x; 1.7774x over previous
#include <cuda_runtime.h>
#include <cstdint>
#include <cstddef>

// Problem constants
#define NB   4
#define TLEN 2048
#define DMODEL 1024
#define NH   16
#define DK   64
#define MROWS (NB * TLEN)        // 8192
#define QKVCOLS (3 * DMODEL)     // 3072

// Scratch (device globals: allocation-free per harness rules)
__device__ float g_qkv[(size_t)MROWS * QKVCOLS];        // 100.7 MB
__device__ float g_att[(size_t)MROWS * DMODEL];         // 33.6 MB
__device__ float g_wtqkv[(size_t)QKVCOLS * DMODEL];     // 12.6 MB  (Wqkv^T, tf32-rounded)
__device__ float g_wtout[(size_t)DMODEL * DMODEL];      // 4.2 MB   (Wout^T, tf32-rounded)

__device__ __forceinline__ float tf32r(float x) {
    uint32_t u;
    asm("cvt.rna.tf32.f32 %0, %1;" : "=r"(u) : "f"(x));
    return __uint_as_float(u);
}

// ===========================================================================
// Weight transpose + tf32 rounding: WT[n][k] = tf32(W[k][n]); W is [K,N] rm.
// ===========================================================================
__global__ __launch_bounds__(256)
void transpose_round_kernel(const float* __restrict__ W, float* __restrict__ WT,
                            int K, int N)
{
    __shared__ float tile[32][33];
    const int bx = blockIdx.x * 32;   // N direction
    const int by = blockIdx.y * 32;   // K direction
    const int tx = threadIdx.x;       // 0..31
    const int ty = threadIdx.y;       // 0..7
#pragma unroll
    for (int i = 0; i < 32; i += 8)
        tile[ty + i][tx] = W[(size_t)(by + ty + i) * N + bx + tx];
    __syncthreads();
#pragma unroll
    for (int i = 0; i < 32; i += 8)
        WT[(size_t)(bx + ty + i) * K + by + tx] = tf32r(tile[tx][ty + i]);
}

// ===========================================================================
// tf32 mma.sync GEMM: C[M,N] = A[M,K] * BT[N,K]^T   (BT pre-rounded tf32)
// CTA tile 128x128, BK=32. 8 warps: 2 (M) x 4 (N); warp tile 64x32.
// smem layout [row][k] with stride 36 (pad 4) -> conflict-free frag loads.
// ===========================================================================
#define SSTRIDE 36

__global__ __launch_bounds__(256, 2)
void tf32_mma_gemm_kernel(const float* __restrict__ A, const float* __restrict__ BT,
                          float* __restrict__ C, int M, int N, int K)
{
    __shared__ float sA[128 * SSTRIDE];
    __shared__ float sB[128 * SSTRIDE];

    const int tid = threadIdx.x;
    const int wid = tid >> 5;
    const int lane = tid & 31;
    const int row0 = blockIdx.y * 128;
    const int col0 = blockIdx.x * 128;

    const int warpM = wid >> 2;          // 0..1
    const int warpN = wid & 3;           // 0..3
    const int qrow = lane >> 2;          // 0..7
    const int qk   = lane & 3;           // 0..3

    // staging mapping: thread -> (row = tid>>3 + 32*i, float4 index kq = tid&7)
    const int skq  = (tid & 7) << 2;     // 0,4,...,28
    const int srow = tid >> 3;           // 0..31

    const float* Abase = A  + (size_t)(row0 + srow) * K + skq;
    const float* Bbase = BT + (size_t)(col0 + srow) * K + skq;

    float c[4][4][4];
#pragma unroll
    for (int mt = 0; mt < 4; mt++)
#pragma unroll
        for (int nt = 0; nt < 4; nt++)
#pragma unroll
            for (int r = 0; r < 4; r++) c[mt][nt][r] = 0.0f;

    // per-warp fragment base addresses in smem
    const float* aFrag[4];
    const float* bFrag[4];
#pragma unroll
    for (int mt = 0; mt < 4; mt++)
        aFrag[mt] = &sA[(warpM * 64 + mt * 16 + qrow) * SSTRIDE + qk];
#pragma unroll
    for (int nt = 0; nt < 4; nt++)
        bFrag[nt] = &sB[(warpN * 32 + nt * 8 + qrow) * SSTRIDE + qk];

    for (int k0 = 0; k0 < K; k0 += 32) {
        __syncthreads();
        // stage A (tf32-round) and BT (already rounded) : 128x32 each
#pragma unroll
        for (int i = 0; i < 4; i++) {
            const int row = srow + (i << 5);
            float4 va = *reinterpret_cast<const float4*>(Abase + (size_t)(i << 5) * K + k0);
            va.x = tf32r(va.x); va.y = tf32r(va.y);
            va.z = tf32r(va.z); va.w = tf32r(va.w);
            *reinterpret_cast<float4*>(&sA[row * SSTRIDE + skq]) = va;
            float4 vb = *reinterpret_cast<const float4*>(Bbase + (size_t)(i << 5) * K + k0);
            *reinterpret_cast<float4*>(&sB[row * SSTRIDE + skq]) = vb;
        }
        __syncthreads();

#pragma unroll
        for (int kk = 0; kk < 32; kk += 8) {
            uint32_t af[4][4], bf[4][2];
#pragma unroll
            for (int mt = 0; mt < 4; mt++) {
                af[mt][0] = __float_as_uint(aFrag[mt][kk]);
                af[mt][1] = __float_as_uint(aFrag[mt][8 * SSTRIDE + kk]);
                af[mt][2] = __float_as_uint(aFrag[mt][kk + 4]);
                af[mt][3] = __float_as_uint(aFrag[mt][8 * SSTRIDE + kk + 4]);
            }
#pragma unroll
            for (int nt = 0; nt < 4; nt++) {
                bf[nt][0] = __float_as_uint(bFrag[nt][kk]);
                bf[nt][1] = __float_as_uint(bFrag[nt][kk + 4]);
            }
#pragma unroll
            for (int mt = 0; mt < 4; mt++)
#pragma unroll
                for (int nt = 0; nt < 4; nt++) {
                    asm volatile(
                        "mma.sync.aligned.m16n8k8.row.col.f32.tf32.tf32.f32 "
                        "{%0,%1,%2,%3}, {%4,%5,%6,%7}, {%8,%9}, {%0,%1,%2,%3};"
                        : "+f"(c[mt][nt][0]), "+f"(c[mt][nt][1]),
                          "+f"(c[mt][nt][2]), "+f"(c[mt][nt][3])
                        : "r"(af[mt][0]), "r"(af[mt][1]), "r"(af[mt][2]), "r"(af[mt][3]),
                          "r"(bf[nt][0]), "r"(bf[nt][1]));
                }
        }
    }

    // epilogue: each thread owns rows (qrow, qrow+8) x 2 cols per (mt,nt)
#pragma unroll
    for (int mt = 0; mt < 4; mt++) {
        const int r = row0 + warpM * 64 + mt * 16 + qrow;
#pragma unroll
        for (int nt = 0; nt < 4; nt++) {
            const int col = col0 + warpN * 32 + nt * 8 + qk * 2;
            float2 v0 = make_float2(c[mt][nt][0], c[mt][nt][1]);
            float2 v1 = make_float2(c[mt][nt][2], c[mt][nt][3]);
            *reinterpret_cast<float2*>(C + (size_t)r * N + col) = v0;
            *reinterpret_cast<float2*>(C + (size_t)(r + 8) * N + col) = v1;
        }
    }
}

// ---------------------------------------------------------------------------
// Flash attention (causal), fp32. One CTA per (q-tile of 64, head, batch).
// (unchanged from round 1 — verified correct)
// ---------------------------------------------------------------------------
__global__ __launch_bounds__(256)
void flash_attn_kernel(const float* __restrict__ qkv, float* __restrict__ attout)
{
    const int qt = blockIdx.x;
    const int h  = blockIdx.y;
    const int n  = blockIdx.z;
    const int tid = threadIdx.x;
    const int tx = tid & 15;
    const int ty = tid >> 4;

    __shared__ float Qt[64][64];
    __shared__ float Kt[64][64];
    __shared__ float Vs[64][64];

    const int lr = tid >> 2;
    const int lc = (tid & 3) << 4;

    const size_t rs = QKVCOLS;
    const float* qbase = qkv + ((size_t)(n * TLEN + qt * 64)) * rs + h * DK;

#pragma unroll
    for (int u = 0; u < 16; u += 4) {
        float4 v = *reinterpret_cast<const float4*>(qbase + (size_t)lr * rs + lc + u);
        Qt[lc + u + 0][lr] = v.x;
        Qt[lc + u + 1][lr] = v.y;
        Qt[lc + u + 2][lr] = v.z;
        Qt[lc + u + 3][lr] = v.w;
    }

    float m[4], l[4], o[4][4];
#pragma unroll
    for (int i = 0; i < 4; i++) {
        m[i] = -1e30f; l[i] = 0.0f;
#pragma unroll
        for (int j = 0; j < 4; j++) o[i][j] = 0.0f;
    }

    const float scale = 0.125f;

    for (int kt = 0; kt <= qt; kt++) {
        __syncthreads();

        const float* kbase = qkv + ((size_t)(n * TLEN + kt * 64)) * rs + DMODEL + h * DK;
        const float* vbase = kbase + DMODEL;
#pragma unroll
        for (int u = 0; u < 16; u += 4) {
            float4 v = *reinterpret_cast<const float4*>(kbase + (size_t)lr * rs + lc + u);
            Kt[lc + u + 0][lr] = v.x;
            Kt[lc + u + 1][lr] = v.y;
            Kt[lc + u + 2][lr] = v.z;
            Kt[lc + u + 3][lr] = v.w;
            float4 w = *reinterpret_cast<const float4*>(vbase + (size_t)lr * rs + lc + u);
            *reinterpret_cast<float4*>(&Vs[lr][lc + u]) = w;
        }
        __syncthreads();

        float s[4][4];
#pragma unroll
        for (int i = 0; i < 4; i++)
#pragma unroll
            for (int j = 0; j < 4; j++) s[i][j] = 0.0f;

#pragma unroll 8
        for (int d = 0; d < 64; d++) {
            float4 qv = *reinterpret_cast<const float4*>(&Qt[d][ty << 2]);
            float4 kv = *reinterpret_cast<const float4*>(&Kt[d][tx << 2]);
            float qa[4] = {qv.x, qv.y, qv.z, qv.w};
            float ka[4] = {kv.x, kv.y, kv.z, kv.w};
#pragma unroll
            for (int i = 0; i < 4; i++)
#pragma unroll
                for (int j = 0; j < 4; j++)
                    s[i][j] = fmaf(qa[i], ka[j], s[i][j]);
        }

        const bool diag = (kt == qt);

#pragma unroll
        for (int i = 0; i < 4; i++) {
            const int qrow = (ty << 2) + i;
            float rm = -1e30f;
#pragma unroll
            for (int j = 0; j < 4; j++) {
                float v = s[i][j] * scale;
                if (diag && ((tx << 2) + j > qrow)) v = -1e30f;
                s[i][j] = v;
                rm = fmaxf(rm, v);
            }
#pragma unroll
            for (int off = 8; off > 0; off >>= 1)
                rm = fmaxf(rm, __shfl_xor_sync(0xffffffffu, rm, off, 16));

            float mn = fmaxf(m[i], rm);
            float corr = __expf(m[i] - mn);
            float rsum = 0.0f;
#pragma unroll
            for (int j = 0; j < 4; j++) {
                float p = __expf(s[i][j] - mn);
                s[i][j] = p;
                rsum += p;
            }
#pragma unroll
            for (int off = 8; off > 0; off >>= 1)
                rsum += __shfl_xor_sync(0xffffffffu, rsum, off, 16);

            l[i] = l[i] * corr + rsum;
            m[i] = mn;
#pragma unroll
            for (int j = 0; j < 4; j++) o[i][j] *= corr;
        }

        __syncthreads();

#pragma unroll
        for (int i = 0; i < 4; i++) {
            float4 pv = make_float4(s[i][0], s[i][1], s[i][2], s[i][3]);
            *reinterpret_cast<float4*>(&Kt[(ty << 2) + i][tx << 2]) = pv;
        }
        __syncthreads();

#pragma unroll 8
        for (int kk = 0; kk < 64; kk++) {
            float4 vv = *reinterpret_cast<const float4*>(&Vs[kk][tx << 2]);
            float va[4] = {vv.x, vv.y, vv.z, vv.w};
            float pa[4];
#pragma unroll
            for (int i = 0; i < 4; i++) pa[i] = Kt[(ty << 2) + i][kk];
#pragma unroll
            for (int i = 0; i < 4; i++)
#pragma unroll
                for (int j = 0; j < 4; j++)
                    o[i][j] = fmaf(pa[i], va[j], o[i][j]);
        }
    }

    float* obase = attout + ((size_t)(n * TLEN + qt * 64)) * DMODEL + h * DK;
#pragma unroll
    for (int i = 0; i < 4; i++) {
        float inv = 1.0f / l[i];
        float* orow = obase + (size_t)((ty << 2) + i) * DMODEL + (tx << 2);
        float4 v = make_float4(o[i][0] * inv, o[i][1] * inv, o[i][2] * inv, o[i][3] * inv);
        *reinterpret_cast<float4*>(orow) = v;
    }
}

// ---------------------------------------------------------------------------
// Launch
// ---------------------------------------------------------------------------
extern "C" void kernel_launch(void* const* d_in, const int* in_sizes, int n_in,
                              void* d_out, int out_size)
{
    const float* z    = (const float*)d_in[0];   // [4,2048,1024]
    const float* Wqkv = (const float*)d_in[1];   // [1024,3072]
    const float* Wout = (const float*)d_in[2];   // [1024,1024]
    float* out = (float*)d_out;                  // [4,2048,1024]

    void *pqkv = nullptr, *patt = nullptr, *pwq = nullptr, *pwo = nullptr;
    cudaGetSymbolAddress(&pqkv, g_qkv);
    cudaGetSymbolAddress(&patt, g_att);
    cudaGetSymbolAddress(&pwq, g_wtqkv);
    cudaGetSymbolAddress(&pwo, g_wtout);
    float* qkv = (float*)pqkv;
    float* att = (float*)patt;
    float* wtq = (float*)pwq;
    float* wto = (float*)pwo;

    // 0) transpose + tf32-round the weights
    transpose_round_kernel<<<dim3(QKVCOLS / 32, DMODEL / 32), dim3(32, 8)>>>(
        Wqkv, wtq, DMODEL, QKVCOLS);
    transpose_round_kernel<<<dim3(DMODEL / 32, DMODEL / 32), dim3(32, 8)>>>(
        Wout, wto, DMODEL, DMODEL);

    // 1) qkv = z @ Wqkv  via tf32 mma.sync
    tf32_mma_gemm_kernel<<<dim3(QKVCOLS / 128, MROWS / 128), 256>>>(
        z, wtq, qkv, MROWS, QKVCOLS, DMODEL);

    // 2) causal flash attention
    flash_attn_kernel<<<dim3(TLEN / 64, NH, NB), 256>>>(qkv, att);

    // 3) out = att @ Wout via tf32 mma.sync
    tf32_mma_gemm_kernel<<<dim3(DMODEL / 128, MROWS / 128), 256>>>(
        att, wto, out, MROWS, DMODEL, DMODEL);
}

// round 4
// speedup vs baseline: 3.6669x; 2.0630x over previous
#include <cuda_runtime.h>
#include <cstdint>
#include <cstddef>

// Problem constants
#define NB   4
#define TLEN 2048
#define DMODEL 1024
#define NH   16
#define DK   64
#define MROWS (NB * TLEN)        // 8192
#define QKVCOLS (3 * DMODEL)     // 3072

// Scratch (device globals: allocation-free per harness rules)
__device__ float g_qkv[(size_t)MROWS * QKVCOLS];        // 100.7 MB
__device__ float g_att[(size_t)MROWS * DMODEL];         // 33.6 MB
__device__ float g_wtqkv[(size_t)QKVCOLS * DMODEL];     // 12.6 MB  (Wqkv^T, tf32-rounded)
__device__ float g_wtout[(size_t)DMODEL * DMODEL];      // 4.2 MB   (Wout^T, tf32-rounded)

__device__ __forceinline__ float tf32r(float x) {
    uint32_t u;
    asm("cvt.rna.tf32.f32 %0, %1;" : "=r"(u) : "f"(x));
    return __uint_as_float(u);
}

#define MMA_TF32(c, a, b)                                                     \
    asm volatile(                                                             \
        "mma.sync.aligned.m16n8k8.row.col.f32.tf32.tf32.f32 "                 \
        "{%0,%1,%2,%3}, {%4,%5,%6,%7}, {%8,%9}, {%0,%1,%2,%3};"               \
        : "+f"((c)[0]), "+f"((c)[1]), "+f"((c)[2]), "+f"((c)[3])              \
        : "r"((a)[0]), "r"((a)[1]), "r"((a)[2]), "r"((a)[3]),                 \
          "r"((b)[0]), "r"((b)[1]))

// ===========================================================================
// Weight transpose + tf32 rounding: WT[n][k] = tf32(W[k][n]); W is [K,N] rm.
// ===========================================================================
__global__ __launch_bounds__(256)
void transpose_round_kernel(const float* __restrict__ W, float* __restrict__ WT,
                            int K, int N)
{
    __shared__ float tile[32][33];
    const int bx = blockIdx.x * 32;
    const int by = blockIdx.y * 32;
    const int tx = threadIdx.x;
    const int ty = threadIdx.y;
#pragma unroll
    for (int i = 0; i < 32; i += 8)
        tile[ty + i][tx] = W[(size_t)(by + ty + i) * N + bx + tx];
    __syncthreads();
#pragma unroll
    for (int i = 0; i < 32; i += 8)
        WT[(size_t)(bx + ty + i) * K + by + tx] = tf32r(tile[tx][ty + i]);
}

// ===========================================================================
// tf32 mma.sync GEMM: C[M,N] = A[M,K] * BT[N,K]^T  (unchanged, verified)
// ===========================================================================
#define SSTRIDE 36

__global__ __launch_bounds__(256, 2)
void tf32_mma_gemm_kernel(const float* __restrict__ A, const float* __restrict__ BT,
                          float* __restrict__ C, int M, int N, int K)
{
    __shared__ float sA[128 * SSTRIDE];
    __shared__ float sB[128 * SSTRIDE];

    const int tid = threadIdx.x;
    const int wid = tid >> 5;
    const int lane = tid & 31;
    const int row0 = blockIdx.y * 128;
    const int col0 = blockIdx.x * 128;

    const int warpM = wid >> 2;
    const int warpN = wid & 3;
    const int qrow = lane >> 2;
    const int qk   = lane & 3;

    const int skq  = (tid & 7) << 2;
    const int srow = tid >> 3;

    const float* Abase = A  + (size_t)(row0 + srow) * K + skq;
    const float* Bbase = BT + (size_t)(col0 + srow) * K + skq;

    float c[4][4][4];
#pragma unroll
    for (int mt = 0; mt < 4; mt++)
#pragma unroll
        for (int nt = 0; nt < 4; nt++)
#pragma unroll
            for (int r = 0; r < 4; r++) c[mt][nt][r] = 0.0f;

    const float* aFrag[4];
    const float* bFrag[4];
#pragma unroll
    for (int mt = 0; mt < 4; mt++)
        aFrag[mt] = &sA[(warpM * 64 + mt * 16 + qrow) * SSTRIDE + qk];
#pragma unroll
    for (int nt = 0; nt < 4; nt++)
        bFrag[nt] = &sB[(warpN * 32 + nt * 8 + qrow) * SSTRIDE + qk];

    for (int k0 = 0; k0 < K; k0 += 32) {
        __syncthreads();
#pragma unroll
        for (int i = 0; i < 4; i++) {
            const int row = srow + (i << 5);
            float4 va = *reinterpret_cast<const float4*>(Abase + (size_t)(i << 5) * K + k0);
            va.x = tf32r(va.x); va.y = tf32r(va.y);
            va.z = tf32r(va.z); va.w = tf32r(va.w);
            *reinterpret_cast<float4*>(&sA[row * SSTRIDE + skq]) = va;
            float4 vb = *reinterpret_cast<const float4*>(Bbase + (size_t)(i << 5) * K + k0);
            *reinterpret_cast<float4*>(&sB[row * SSTRIDE + skq]) = vb;
        }
        __syncthreads();

#pragma unroll
        for (int kk = 0; kk < 32; kk += 8) {
            uint32_t af[4][4], bf[4][2];
#pragma unroll
            for (int mt = 0; mt < 4; mt++) {
                af[mt][0] = __float_as_uint(aFrag[mt][kk]);
                af[mt][1] = __float_as_uint(aFrag[mt][8 * SSTRIDE + kk]);
                af[mt][2] = __float_as_uint(aFrag[mt][kk + 4]);
                af[mt][3] = __float_as_uint(aFrag[mt][8 * SSTRIDE + kk + 4]);
            }
#pragma unroll
            for (int nt = 0; nt < 4; nt++) {
                bf[nt][0] = __float_as_uint(bFrag[nt][kk]);
                bf[nt][1] = __float_as_uint(bFrag[nt][kk + 4]);
            }
#pragma unroll
            for (int mt = 0; mt < 4; mt++)
#pragma unroll
                for (int nt = 0; nt < 4; nt++)
                    MMA_TF32(c[mt][nt], af[mt], bf[nt]);
        }
    }

#pragma unroll
    for (int mt = 0; mt < 4; mt++) {
        const int r = row0 + warpM * 64 + mt * 16 + qrow;
#pragma unroll
        for (int nt = 0; nt < 4; nt++) {
            const int col = col0 + warpN * 32 + nt * 8 + qk * 2;
            *reinterpret_cast<float2*>(C + (size_t)r * N + col) =
                make_float2(c[mt][nt][0], c[mt][nt][1]);
            *reinterpret_cast<float2*>(C + (size_t)(r + 8) * N + col) =
                make_float2(c[mt][nt][2], c[mt][nt][3]);
        }
    }
}

// ===========================================================================
// Tensor-core causal flash attention (tf32 mma.sync).
// CTA: 128 q-rows, loop over 64-wide kv tiles. 8 warps, 16 q-rows each.
// smem: K[64][68], V[64][72], P[128][68] (P buffer doubles as Q staging).
// ===========================================================================
#define KSTR 68
#define VSTR 72
#define PSTR 68
#define FLASH_SMEM ((64 * KSTR + 64 * VSTR + 128 * PSTR) * 4)

__global__ __launch_bounds__(256, 2)
void flash_attn_tc_kernel(const float* __restrict__ qkv, float* __restrict__ attout)
{
    extern __shared__ float smem[];
    float* sK = smem;                       // [64][KSTR]
    float* sV = smem + 64 * KSTR;           // [64][VSTR]
    float* sP = smem + 64 * KSTR + 64 * VSTR; // [128][PSTR]

    const int qb = (int)gridDim.x - 1 - (int)blockIdx.x;  // heavy tiles first
    const int h = blockIdx.y;
    const int n = blockIdx.z;
    const int tid = threadIdx.x;
    const int wid = tid >> 5;
    const int lane = tid & 31;
    const int qrow = lane >> 2;
    const int qk = lane & 3;
    const int q0 = qb * 128;

    const size_t rs = QKVCOLS;

    // ---- stage Q (tf32-rounded) into sP -----------------------------------
    {
        const int c4 = (tid & 15) << 2;    // 0..60
        const int r0 = tid >> 4;           // 0..15
        const float* qg = qkv + ((size_t)(n * TLEN + q0 + r0)) * rs + h * DK + c4;
        float* ps = sP + r0 * PSTR + c4;
#pragma unroll
        for (int r = 0; r < 8; r++) {
            float4 v = *reinterpret_cast<const float4*>(qg + (size_t)(16 * r) * rs);
            v.x = tf32r(v.x); v.y = tf32r(v.y);
            v.z = tf32r(v.z); v.w = tf32r(v.w);
            *reinterpret_cast<float4*>(ps + 16 * r * PSTR) = v;
        }
    }
    __syncthreads();

    // ---- Q fragments into registers (warp-private rows) -------------------
    uint32_t qf[8][4];
    {
        const float* qbse = sP + (wid * 16 + qrow) * PSTR + qk;
#pragma unroll
        for (int kc = 0; kc < 8; kc++) {
            qf[kc][0] = __float_as_uint(qbse[8 * kc]);
            qf[kc][1] = __float_as_uint(qbse[8 * PSTR + 8 * kc]);
            qf[kc][2] = __float_as_uint(qbse[8 * kc + 4]);
            qf[kc][3] = __float_as_uint(qbse[8 * PSTR + 8 * kc + 4]);
        }
    }

    float o[8][4];
#pragma unroll
    for (int nt = 0; nt < 8; nt++)
#pragma unroll
        for (int r = 0; r < 4; r++) o[nt][r] = 0.0f;

    float m0 = -1e30f, m1 = -1e30f, l0 = 0.0f, l1 = 0.0f;

    const int q_abs0 = q0 + wid * 16 + qrow;   // row half 0
    const int q_abs1 = q_abs0 + 8;             // row half 1
    const int wmax_kt = (q0 + wid * 16 + 15) >> 6;  // last active tile for warp
    const int ntiles = 2 * qb + 2;
    const float scale = 0.125f;

    for (int kt = 0; kt < ntiles; kt++) {
        __syncthreads();   // prior S (K reads) + PV (V reads) complete

        // ---- stage K, V (tf32-rounded) ----
        {
            const int c4 = (tid & 15) << 2;
            const int r0 = tid >> 4;
            const float* kg = qkv + ((size_t)(n * TLEN + kt * 64 + r0)) * rs
                              + DMODEL + h * DK + c4;
            const float* vg = kg + DMODEL;
#pragma unroll
            for (int r = 0; r < 4; r++) {
                float4 a = *reinterpret_cast<const float4*>(kg + (size_t)(16 * r) * rs);
                a.x = tf32r(a.x); a.y = tf32r(a.y);
                a.z = tf32r(a.z); a.w = tf32r(a.w);
                *reinterpret_cast<float4*>(sK + (r0 + 16 * r) * KSTR + c4) = a;
                float4 b = *reinterpret_cast<const float4*>(vg + (size_t)(16 * r) * rs);
                b.x = tf32r(b.x); b.y = tf32r(b.y);
                b.z = tf32r(b.z); b.w = tf32r(b.w);
                *reinterpret_cast<float4*>(sV + (r0 + 16 * r) * VSTR + c4) = b;
            }
        }
        __syncthreads();

        if (kt > wmax_kt) continue;   // warp fully above diagonal for this tile

        // ---- S = Q K^T ----
        float s[8][4];
#pragma unroll
        for (int nt = 0; nt < 8; nt++)
#pragma unroll
            for (int r = 0; r < 4; r++) s[nt][r] = 0.0f;

#pragma unroll
        for (int kc = 0; kc < 8; kc++) {
#pragma unroll
            for (int nt = 0; nt < 8; nt++) {
                uint32_t bK[2];
                bK[0] = __float_as_uint(sK[(nt * 8 + qrow) * KSTR + 8 * kc + qk]);
                bK[1] = __float_as_uint(sK[(nt * 8 + qrow) * KSTR + 8 * kc + qk + 4]);
                MMA_TF32(s[nt], qf[kc], bK);
            }
        }

        // ---- online softmax ----
        const bool needmask = ((kt << 6) + 63) > (q0 + wid * 16);  // warp-uniform

#pragma unroll
        for (int nt = 0; nt < 8; nt++) {
            s[nt][0] *= scale; s[nt][1] *= scale;
            s[nt][2] *= scale; s[nt][3] *= scale;
        }
        if (needmask) {
#pragma unroll
            for (int nt = 0; nt < 8; nt++) {
                const int c0 = (kt << 6) + (nt << 3) + (qk << 1);
                if (c0     > q_abs0) s[nt][0] = -1e30f;
                if (c0 + 1 > q_abs0) s[nt][1] = -1e30f;
                if (c0     > q_abs1) s[nt][2] = -1e30f;
                if (c0 + 1 > q_abs1) s[nt][3] = -1e30f;
            }
        }

        float rm0 = -1e30f, rm1 = -1e30f;
#pragma unroll
        for (int nt = 0; nt < 8; nt++) {
            rm0 = fmaxf(rm0, fmaxf(s[nt][0], s[nt][1]));
            rm1 = fmaxf(rm1, fmaxf(s[nt][2], s[nt][3]));
        }
        rm0 = fmaxf(rm0, __shfl_xor_sync(0xffffffffu, rm0, 1));
        rm0 = fmaxf(rm0, __shfl_xor_sync(0xffffffffu, rm0, 2));
        rm1 = fmaxf(rm1, __shfl_xor_sync(0xffffffffu, rm1, 1));
        rm1 = fmaxf(rm1, __shfl_xor_sync(0xffffffffu, rm1, 2));

        const float mn0 = fmaxf(m0, rm0);
        const float mn1 = fmaxf(m1, rm1);
        const float corr0 = __expf(m0 - mn0);
        const float corr1 = __expf(m1 - mn1);
        m0 = mn0; m1 = mn1;

        float rs0 = 0.0f, rs1 = 0.0f;
#pragma unroll
        for (int nt = 0; nt < 8; nt++) {
            s[nt][0] = __expf(s[nt][0] - mn0);
            s[nt][1] = __expf(s[nt][1] - mn0);
            s[nt][2] = __expf(s[nt][2] - mn1);
            s[nt][3] = __expf(s[nt][3] - mn1);
            rs0 += s[nt][0] + s[nt][1];
            rs1 += s[nt][2] + s[nt][3];
        }
        rs0 += __shfl_xor_sync(0xffffffffu, rs0, 1);
        rs0 += __shfl_xor_sync(0xffffffffu, rs0, 2);
        rs1 += __shfl_xor_sync(0xffffffffu, rs1, 1);
        rs1 += __shfl_xor_sync(0xffffffffu, rs1, 2);

        l0 = l0 * corr0 + rs0;
        l1 = l1 * corr1 + rs1;

#pragma unroll
        for (int nt = 0; nt < 8; nt++) {
            o[nt][0] *= corr0; o[nt][1] *= corr0;
            o[nt][2] *= corr1; o[nt][3] *= corr1;
        }

        // ---- P -> smem (warp-private rows), tf32-rounded ----
        {
            float* pw = sP + (wid * 16 + qrow) * PSTR + (qk << 1);
#pragma unroll
            for (int nt = 0; nt < 8; nt++) {
                *reinterpret_cast<float2*>(pw + nt * 8) =
                    make_float2(tf32r(s[nt][0]), tf32r(s[nt][1]));
                *reinterpret_cast<float2*>(pw + 8 * PSTR + nt * 8) =
                    make_float2(tf32r(s[nt][2]), tf32r(s[nt][3]));
            }
        }
        __syncwarp();

        // ---- O += P V ----
        {
            const float* pa = sP + (wid * 16 + qrow) * PSTR + qk;
#pragma unroll
            for (int kvc = 0; kvc < 8; kvc++) {
                uint32_t af[4];
                af[0] = __float_as_uint(pa[kvc * 8]);
                af[1] = __float_as_uint(pa[8 * PSTR + kvc * 8]);
                af[2] = __float_as_uint(pa[kvc * 8 + 4]);
                af[3] = __float_as_uint(pa[8 * PSTR + kvc * 8 + 4]);
                const float* vb = sV + (kvc * 8 + qk) * VSTR + qrow;
#pragma unroll
                for (int nt = 0; nt < 8; nt++) {
                    uint32_t bV[2];
                    bV[0] = __float_as_uint(vb[nt * 8]);
                    bV[1] = __float_as_uint(vb[4 * VSTR + nt * 8]);
                    MMA_TF32(o[nt], af, bV);
                }
            }
        }
        __syncwarp();   // P reads done before next iteration overwrites
    }

    // ---- epilogue: normalize + store ----
    const float inv0 = 1.0f / l0;
    const float inv1 = 1.0f / l1;
    float* ob = attout + ((size_t)(n * TLEN + q0 + wid * 16 + qrow)) * DMODEL
                + h * DK + (qk << 1);
#pragma unroll
    for (int nt = 0; nt < 8; nt++) {
        *reinterpret_cast<float2*>(ob + nt * 8) =
            make_float2(o[nt][0] * inv0, o[nt][1] * inv0);
        *reinterpret_cast<float2*>(ob + (size_t)8 * DMODEL + nt * 8) =
            make_float2(o[nt][2] * inv1, o[nt][3] * inv1);
    }
}

// ---------------------------------------------------------------------------
// Launch
// ---------------------------------------------------------------------------
extern "C" void kernel_launch(void* const* d_in, const int* in_sizes, int n_in,
                              void* d_out, int out_size)
{
    const float* z    = (const float*)d_in[0];
    const float* Wqkv = (const float*)d_in[1];
    const float* Wout = (const float*)d_in[2];
    float* out = (float*)d_out;

    void *pqkv = nullptr, *patt = nullptr, *pwq = nullptr, *pwo = nullptr;
    cudaGetSymbolAddress(&pqkv, g_qkv);
    cudaGetSymbolAddress(&patt, g_att);
    cudaGetSymbolAddress(&pwq, g_wtqkv);
    cudaGetSymbolAddress(&pwo, g_wtout);
    float* qkv = (float*)pqkv;
    float* att = (float*)patt;
    float* wtq = (float*)pwq;
    float* wto = (float*)pwo;

    cudaFuncSetAttribute(flash_attn_tc_kernel,
                         cudaFuncAttributeMaxDynamicSharedMemorySize, FLASH_SMEM);

    // 0) transpose + tf32-round the weights
    transpose_round_kernel<<<dim3(QKVCOLS / 32, DMODEL / 32), dim3(32, 8)>>>(
        Wqkv, wtq, DMODEL, QKVCOLS);
    transpose_round_kernel<<<dim3(DMODEL / 32, DMODEL / 32), dim3(32, 8)>>>(
        Wout, wto, DMODEL, DMODEL);

    // 1) qkv = z @ Wqkv  via tf32 mma.sync
    tf32_mma_gemm_kernel<<<dim3(QKVCOLS / 128, MROWS / 128), 256>>>(
        z, wtq, qkv, MROWS, QKVCOLS, DMODEL);

    // 2) causal flash attention on tensor cores
    flash_attn_tc_kernel<<<dim3(TLEN / 128, NH, NB), 256, FLASH_SMEM>>>(qkv, att);

    // 3) out = att @ Wout via tf32 mma.sync
    tf32_mma_gemm_kernel<<<dim3(DMODEL / 128, MROWS / 128), 256>>>(
        att, wto, out, MROWS, DMODEL, DMODEL);
}

// round 5
// speedup vs baseline: 3.8173x; 1.0410x over previous
#include <cuda_runtime.h>
#include <cstdint>
#include <cstddef>

// Problem constants
#define NB   4
#define TLEN 2048
#define DMODEL 1024
#define NH   16
#define DK   64
#define MROWS (NB * TLEN)        // 8192
#define QKVCOLS (3 * DMODEL)     // 3072

// Q pre-scale: 1/sqrt(64) * log2(e)  (softmax runs in exp2 domain)
#define QSCALE 0.1803368801111204f

// Scratch (device globals: allocation-free per harness rules)
__device__ float g_qkv[(size_t)MROWS * QKVCOLS];        // 100.7 MB (tf32, Q pre-scaled)
__device__ float g_att[(size_t)MROWS * DMODEL];         // 33.6 MB  (tf32)
__device__ float g_zr[(size_t)MROWS * DMODEL];          // 33.6 MB  (z, tf32-rounded)
__device__ float g_wtqkv[(size_t)QKVCOLS * DMODEL];     // 12.6 MB  (Wqkv^T, tf32)
__device__ float g_wtout[(size_t)DMODEL * DMODEL];      // 4.2 MB   (Wout^T, tf32)

__device__ __forceinline__ float tf32r(float x) {
    uint32_t u;
    asm("cvt.rna.tf32.f32 %0, %1;" : "=r"(u) : "f"(x));
    return __uint_as_float(u);
}

__device__ __forceinline__ float ex2(float x) {
    float y;
    asm("ex2.approx.f32 %0, %1;" : "=f"(y) : "f"(x));
    return y;
}

__device__ __forceinline__ uint32_t smem_u32(const void* p) {
    uint32_t a;
    asm("{ .reg .u64 t; cvta.to.shared.u64 t, %1; cvt.u32.u64 %0, t; }"
        : "=r"(a) : "l"(p));
    return a;
}

__device__ __forceinline__ void cp16(uint32_t dst, const void* src) {
    asm volatile("cp.async.cg.shared.global [%0], [%1], 16;"
                 :: "r"(dst), "l"(src));
}
#define CP_COMMIT() asm volatile("cp.async.commit_group;" ::: "memory")
#define CP_WAIT0()  asm volatile("cp.async.wait_group 0;" ::: "memory")

#define MMA_TF32(c, a, b)                                                     \
    asm volatile(                                                             \
        "mma.sync.aligned.m16n8k8.row.col.f32.tf32.tf32.f32 "                 \
        "{%0,%1,%2,%3}, {%4,%5,%6,%7}, {%8,%9}, {%0,%1,%2,%3};"               \
        : "+f"((c)[0]), "+f"((c)[1]), "+f"((c)[2]), "+f"((c)[3])              \
        : "r"((a)[0]), "r"((a)[1]), "r"((a)[2]), "r"((a)[3]),                 \
          "r"((b)[0]), "r"((b)[1]))

// ===========================================================================
// z -> tf32-rounded copy (so GEMM1 can cp.async raw data)
// ===========================================================================
__global__ __launch_bounds__(256)
void round_copy_kernel(const float4* __restrict__ in, float4* __restrict__ out, int n4)
{
    int i = blockIdx.x * blockDim.x + threadIdx.x;
    if (i < n4) {
        float4 v = in[i];
        v.x = tf32r(v.x); v.y = tf32r(v.y);
        v.z = tf32r(v.z); v.w = tf32r(v.w);
        out[i] = v;
    }
}

// ===========================================================================
// Weight transpose + tf32 rounding: WT[n][k] = tf32(W[k][n]); W is [K,N] rm.
// ===========================================================================
__global__ __launch_bounds__(256)
void transpose_round_kernel(const float* __restrict__ W, float* __restrict__ WT,
                            int K, int N)
{
    __shared__ float tile[32][33];
    const int bx = blockIdx.x * 32;
    const int by = blockIdx.y * 32;
    const int tx = threadIdx.x;
    const int ty = threadIdx.y;
#pragma unroll
    for (int i = 0; i < 32; i += 8)
        tile[ty + i][tx] = W[(size_t)(by + ty + i) * N + bx + tx];
    __syncthreads();
#pragma unroll
    for (int i = 0; i < 32; i += 8)
        WT[(size_t)(bx + ty + i) * K + by + tx] = tf32r(tile[tx][ty + i]);
}

// ===========================================================================
// Pipelined tf32 GEMM: C[M,N] = A[M,K] * BT[N,K]^T.
// A and BT pre-rounded tf32 in gmem -> raw cp.async double-buffered staging.
// CTA tile 128x128, BK=32, 8 warps (2Mx4N), warp tile 64x32.
// roundOut: round C to tf32 (and scale cols < qlimit by qscale).
// ===========================================================================
#define SSTRIDE 36
#define GEMM_SMEM (4 * 128 * SSTRIDE * 4)   // 2 bufs x (sA+sB)

__global__ __launch_bounds__(256, 2)
void tf32_gemm_pipe_kernel(const float* __restrict__ A, const float* __restrict__ BT,
                           float* __restrict__ C, int M, int N, int K,
                           int roundOut, int qlimit, float qscale)
{
    extern __shared__ float gs[];
    float* sA = gs;                        // [2][128*SSTRIDE]
    float* sB = gs + 2 * 128 * SSTRIDE;    // [2][128*SSTRIDE]

    const int tid = threadIdx.x;
    const int wid = tid >> 5;
    const int lane = tid & 31;
    const int row0 = blockIdx.y * 128;
    const int col0 = blockIdx.x * 128;

    const int warpM = wid >> 2;
    const int warpN = wid & 3;
    const int qrow = lane >> 2;
    const int qk   = lane & 3;

    const int skq  = (tid & 7) << 2;
    const int srow = tid >> 3;

    const float* Abase = A  + (size_t)(row0 + srow) * K + skq;
    const float* Bbase = BT + (size_t)(col0 + srow) * K + skq;

    const uint32_t dA0 = smem_u32(sA) + (uint32_t)(srow * SSTRIDE + skq) * 4u;
    const uint32_t dB0 = smem_u32(sB) + (uint32_t)(srow * SSTRIDE + skq) * 4u;
    const uint32_t BUFB = 128u * SSTRIDE * 4u;

    float c[4][4][4];
#pragma unroll
    for (int mt = 0; mt < 4; mt++)
#pragma unroll
        for (int nt = 0; nt < 4; nt++)
#pragma unroll
            for (int r = 0; r < 4; r++) c[mt][nt][r] = 0.0f;

    int aIdx[4], bIdx[4];
#pragma unroll
    for (int mt = 0; mt < 4; mt++)
        aIdx[mt] = (warpM * 64 + mt * 16 + qrow) * SSTRIDE + qk;
#pragma unroll
    for (int nt = 0; nt < 4; nt++)
        bIdx[nt] = (warpN * 32 + nt * 8 + qrow) * SSTRIDE + qk;

    // prologue: prefetch chunk 0 into buffer 0
#pragma unroll
    for (int i = 0; i < 4; i++) {
        cp16(dA0 + (uint32_t)(i * 32 * SSTRIDE) * 4u, Abase + (size_t)(i * 32) * K);
        cp16(dB0 + (uint32_t)(i * 32 * SSTRIDE) * 4u, Bbase + (size_t)(i * 32) * K);
    }
    CP_COMMIT();

    const int niter = K >> 5;
    for (int it = 0; it < niter; it++) {
        CP_WAIT0();
        __syncthreads();
        if (it + 1 < niter) {
            const int k0 = (it + 1) << 5;
            const uint32_t bo = ((it + 1) & 1) * BUFB;
#pragma unroll
            for (int i = 0; i < 4; i++) {
                cp16(dA0 + bo + (uint32_t)(i * 32 * SSTRIDE) * 4u,
                     Abase + (size_t)(i * 32) * K + k0);
                cp16(dB0 + bo + (uint32_t)(i * 32 * SSTRIDE) * 4u,
                     Bbase + (size_t)(i * 32) * K + k0);
            }
            CP_COMMIT();
        }

        const float* a0 = sA + (it & 1) * 128 * SSTRIDE;
        const float* b0 = sB + (it & 1) * 128 * SSTRIDE;

#pragma unroll
        for (int kk = 0; kk < 32; kk += 8) {
            uint32_t af[4][4], bf[4][2];
#pragma unroll
            for (int mt = 0; mt < 4; mt++) {
                af[mt][0] = __float_as_uint(a0[aIdx[mt] + kk]);
                af[mt][1] = __float_as_uint(a0[aIdx[mt] + 8 * SSTRIDE + kk]);
                af[mt][2] = __float_as_uint(a0[aIdx[mt] + kk + 4]);
                af[mt][3] = __float_as_uint(a0[aIdx[mt] + 8 * SSTRIDE + kk + 4]);
            }
#pragma unroll
            for (int nt = 0; nt < 4; nt++) {
                bf[nt][0] = __float_as_uint(b0[bIdx[nt] + kk]);
                bf[nt][1] = __float_as_uint(b0[bIdx[nt] + kk + 4]);
            }
#pragma unroll
            for (int mt = 0; mt < 4; mt++)
#pragma unroll
                for (int nt = 0; nt < 4; nt++)
                    MMA_TF32(c[mt][nt], af[mt], bf[nt]);
        }
    }

    const float fac = (col0 < qlimit) ? qscale : 1.0f;
#pragma unroll
    for (int mt = 0; mt < 4; mt++) {
        const int r = row0 + warpM * 64 + mt * 16 + qrow;
#pragma unroll
        for (int nt = 0; nt < 4; nt++) {
            const int col = col0 + warpN * 32 + nt * 8 + qk * 2;
            float2 v0, v1;
            if (roundOut) {
                v0 = make_float2(tf32r(c[mt][nt][0] * fac), tf32r(c[mt][nt][1] * fac));
                v1 = make_float2(tf32r(c[mt][nt][2] * fac), tf32r(c[mt][nt][3] * fac));
            } else {
                v0 = make_float2(c[mt][nt][0], c[mt][nt][1]);
                v1 = make_float2(c[mt][nt][2], c[mt][nt][3]);
            }
            *reinterpret_cast<float2*>(C + (size_t)r * N + col) = v0;
            *reinterpret_cast<float2*>(C + (size_t)(r + 8) * N + col) = v1;
        }
    }
}

// ===========================================================================
// Tensor-core causal flash attention, cp.async double-buffered K/V,
// softmax in exp2 domain (Q pre-scaled by QSCALE in gmem, all tf32).
// CTA: 128 q-rows; 8 warps, 16 q-rows each. Output rounded to tf32.
// ===========================================================================
#define KSTR 68
#define VSTR 72
#define PSTR 68
#define KBUF (64 * KSTR)
#define VBUF (64 * VSTR)
#define FLASH_SMEM ((2 * KBUF + 2 * VBUF + 128 * PSTR) * 4)

__global__ __launch_bounds__(256, 2)
void flash_attn_tc2_kernel(const float* __restrict__ qkv, float* __restrict__ attout)
{
    extern __shared__ float smem[];
    float* sK = smem;                       // [2][64][KSTR]
    float* sV = smem + 2 * KBUF;            // [2][64][VSTR]
    float* sP = smem + 2 * KBUF + 2 * VBUF; // [128][PSTR]

    const int qb = (int)gridDim.x - 1 - (int)blockIdx.x;  // heavy tiles first
    const int h = blockIdx.y;
    const int n = blockIdx.z;
    const int tid = threadIdx.x;
    const int wid = tid >> 5;
    const int lane = tid & 31;
    const int qrow = lane >> 2;
    const int qk = lane & 3;
    const int q0 = qb * 128;

    const size_t rs = QKVCOLS;
    const int ntiles = 2 * qb + 2;

    // staging thread mapping (shared by Q/K/V): 16 cols x 16 rows per pass
    const int c4 = (tid & 15) << 2;   // 0..60
    const int r0 = tid >> 4;          // 0..15

    const float* kg0 = qkv + ((size_t)(n * TLEN) + r0) * rs + DMODEL + h * DK + c4;
    const uint32_t dK0 = smem_u32(sK) + (uint32_t)(r0 * KSTR + c4) * 4u;
    const uint32_t dV0 = smem_u32(sV) + (uint32_t)(r0 * VSTR + c4) * 4u;

    // prefetch K/V tile 0 into buffer 0
    {
        const float* kg = kg0;
        const float* vg = kg0 + DMODEL;
#pragma unroll
        for (int r = 0; r < 4; r++) {
            cp16(dK0 + (uint32_t)(16 * r * KSTR) * 4u, kg + (size_t)(16 * r) * rs);
            cp16(dV0 + (uint32_t)(16 * r * VSTR) * 4u, vg + (size_t)(16 * r) * rs);
        }
        CP_COMMIT();
    }

    // stage Q (pre-scaled tf32 in gmem; plain copy)
    {
        const float* qg = qkv + ((size_t)(n * TLEN + q0 + r0)) * rs + h * DK + c4;
        float* ps = sP + r0 * PSTR + c4;
#pragma unroll
        for (int r = 0; r < 8; r++)
            *reinterpret_cast<float4*>(ps + 16 * r * PSTR) =
                *reinterpret_cast<const float4*>(qg + (size_t)(16 * r) * rs);
    }
    __syncthreads();

    // Q fragments into registers (warp-private rows)
    uint32_t qf[8][4];
    {
        const float* qbse = sP + (wid * 16 + qrow) * PSTR + qk;
#pragma unroll
        for (int kc = 0; kc < 8; kc++) {
            qf[kc][0] = __float_as_uint(qbse[8 * kc]);
            qf[kc][1] = __float_as_uint(qbse[8 * PSTR + 8 * kc]);
            qf[kc][2] = __float_as_uint(qbse[8 * kc + 4]);
            qf[kc][3] = __float_as_uint(qbse[8 * PSTR + 8 * kc + 4]);
        }
    }

    float o[8][4];
#pragma unroll
    for (int nt = 0; nt < 8; nt++)
#pragma unroll
        for (int r = 0; r < 4; r++) o[nt][r] = 0.0f;

    float m0 = -1e30f, m1 = -1e30f, l0 = 0.0f, l1 = 0.0f;

    const int q_abs0 = q0 + wid * 16 + qrow;
    const int q_abs1 = q_abs0 + 8;
    const int wmax_kt = (q0 + wid * 16 + 15) >> 6;

    for (int kt = 0; kt < ntiles; kt++) {
        CP_WAIT0();
        __syncthreads();   // buf[kt&1] visible; all threads done with buf[(kt+1)&1]

        if (kt + 1 < ntiles) {
            const uint32_t bK = ((kt + 1) & 1) * (uint32_t)(KBUF * 4);
            const uint32_t bV = ((kt + 1) & 1) * (uint32_t)(VBUF * 4);
            const float* kg = kg0 + (size_t)((kt + 1) * 64) * rs;
            const float* vg = kg + DMODEL;
#pragma unroll
            for (int r = 0; r < 4; r++) {
                cp16(dK0 + bK + (uint32_t)(16 * r * KSTR) * 4u, kg + (size_t)(16 * r) * rs);
                cp16(dV0 + bV + (uint32_t)(16 * r * VSTR) * 4u, vg + (size_t)(16 * r) * rs);
            }
            CP_COMMIT();
        }

        if (kt > wmax_kt) continue;   // warp fully above diagonal

        const float* Kb = sK + (kt & 1) * KBUF;
        const float* Vb = sV + (kt & 1) * VBUF;

        // ---- S = Q K^T (already in exp2 domain) ----
        float s[8][4];
#pragma unroll
        for (int nt = 0; nt < 8; nt++)
#pragma unroll
            for (int r = 0; r < 4; r++) s[nt][r] = 0.0f;

#pragma unroll
        for (int kc = 0; kc < 8; kc++) {
#pragma unroll
            for (int nt = 0; nt < 8; nt++) {
                uint32_t bKf[2];
                bKf[0] = __float_as_uint(Kb[(nt * 8 + qrow) * KSTR + 8 * kc + qk]);
                bKf[1] = __float_as_uint(Kb[(nt * 8 + qrow) * KSTR + 8 * kc + qk + 4]);
                MMA_TF32(s[nt], qf[kc], bKf);
            }
        }

        // ---- causal mask (diagonal-straddling tiles only; warp-uniform) ----
        if (((kt << 6) + 63) > (q0 + wid * 16)) {
#pragma unroll
            for (int nt = 0; nt < 8; nt++) {
                const int c0 = (kt << 6) + (nt << 3) + (qk << 1);
                if (c0     > q_abs0) s[nt][0] = -1e30f;
                if (c0 + 1 > q_abs0) s[nt][1] = -1e30f;
                if (c0     > q_abs1) s[nt][2] = -1e30f;
                if (c0 + 1 > q_abs1) s[nt][3] = -1e30f;
            }
        }

        // ---- online softmax (exp2 domain) ----
        float rm0 = -1e30f, rm1 = -1e30f;
#pragma unroll
        for (int nt = 0; nt < 8; nt++) {
            rm0 = fmaxf(rm0, fmaxf(s[nt][0], s[nt][1]));
            rm1 = fmaxf(rm1, fmaxf(s[nt][2], s[nt][3]));
        }
        rm0 = fmaxf(rm0, __shfl_xor_sync(0xffffffffu, rm0, 1));
        rm0 = fmaxf(rm0, __shfl_xor_sync(0xffffffffu, rm0, 2));
        rm1 = fmaxf(rm1, __shfl_xor_sync(0xffffffffu, rm1, 1));
        rm1 = fmaxf(rm1, __shfl_xor_sync(0xffffffffu, rm1, 2));

        const float mn0 = fmaxf(m0, rm0);
        const float mn1 = fmaxf(m1, rm1);
        const float corr0 = ex2(m0 - mn0);
        const float corr1 = ex2(m1 - mn1);
        m0 = mn0; m1 = mn1;

        float rs0 = 0.0f, rs1 = 0.0f;
#pragma unroll
        for (int nt = 0; nt < 8; nt++) {
            s[nt][0] = ex2(s[nt][0] - mn0);
            s[nt][1] = ex2(s[nt][1] - mn0);
            s[nt][2] = ex2(s[nt][2] - mn1);
            s[nt][3] = ex2(s[nt][3] - mn1);
            rs0 += s[nt][0] + s[nt][1];
            rs1 += s[nt][2] + s[nt][3];
        }
        rs0 += __shfl_xor_sync(0xffffffffu, rs0, 1);
        rs0 += __shfl_xor_sync(0xffffffffu, rs0, 2);
        rs1 += __shfl_xor_sync(0xffffffffu, rs1, 1);
        rs1 += __shfl_xor_sync(0xffffffffu, rs1, 2);

        l0 = l0 * corr0 + rs0;
        l1 = l1 * corr1 + rs1;

#pragma unroll
        for (int nt = 0; nt < 8; nt++) {
            o[nt][0] *= corr0; o[nt][1] *= corr0;
            o[nt][2] *= corr1; o[nt][3] *= corr1;
        }

        // ---- P -> smem (warp-private rows), tf32-rounded ----
        {
            float* pw = sP + (wid * 16 + qrow) * PSTR + (qk << 1);
#pragma unroll
            for (int nt = 0; nt < 8; nt++) {
                *reinterpret_cast<float2*>(pw + nt * 8) =
                    make_float2(tf32r(s[nt][0]), tf32r(s[nt][1]));
                *reinterpret_cast<float2*>(pw + 8 * PSTR + nt * 8) =
                    make_float2(tf32r(s[nt][2]), tf32r(s[nt][3]));
            }
        }
        __syncwarp();

        // ---- O += P V ----
        {
            const float* pa = sP + (wid * 16 + qrow) * PSTR + qk;
#pragma unroll
            for (int kvc = 0; kvc < 8; kvc++) {
                uint32_t af[4];
                af[0] = __float_as_uint(pa[kvc * 8]);
                af[1] = __float_as_uint(pa[8 * PSTR + kvc * 8]);
                af[2] = __float_as_uint(pa[kvc * 8 + 4]);
                af[3] = __float_as_uint(pa[8 * PSTR + kvc * 8 + 4]);
                const float* vb = Vb + (kvc * 8 + qk) * VSTR + qrow;
#pragma unroll
                for (int nt = 0; nt < 8; nt++) {
                    uint32_t bV[2];
                    bV[0] = __float_as_uint(vb[nt * 8]);
                    bV[1] = __float_as_uint(vb[4 * VSTR + nt * 8]);
                    MMA_TF32(o[nt], af, bV);
                }
            }
        }
        __syncwarp();
    }

    // ---- epilogue: normalize, round to tf32 (feeds GEMM2 cp.async), store ----
    const float inv0 = 1.0f / l0;
    const float inv1 = 1.0f / l1;
    float* ob = attout + ((size_t)(n * TLEN + q0 + wid * 16 + qrow)) * DMODEL
                + h * DK + (qk << 1);
#pragma unroll
    for (int nt = 0; nt < 8; nt++) {
        *reinterpret_cast<float2*>(ob + nt * 8) =
            make_float2(tf32r(o[nt][0] * inv0), tf32r(o[nt][1] * inv0));
        *reinterpret_cast<float2*>(ob + (size_t)8 * DMODEL + nt * 8) =
            make_float2(tf32r(o[nt][2] * inv1), tf32r(o[nt][3] * inv1));
    }
}

// ---------------------------------------------------------------------------
// Launch
// ---------------------------------------------------------------------------
extern "C" void kernel_launch(void* const* d_in, const int* in_sizes, int n_in,
                              void* d_out, int out_size)
{
    const float* z    = (const float*)d_in[0];
    const float* Wqkv = (const float*)d_in[1];
    const float* Wout = (const float*)d_in[2];
    float* out = (float*)d_out;

    void *pqkv = nullptr, *patt = nullptr, *pzr = nullptr, *pwq = nullptr, *pwo = nullptr;
    cudaGetSymbolAddress(&pqkv, g_qkv);
    cudaGetSymbolAddress(&patt, g_att);
    cudaGetSymbolAddress(&pzr, g_zr);
    cudaGetSymbolAddress(&pwq, g_wtqkv);
    cudaGetSymbolAddress(&pwo, g_wtout);
    float* qkv = (float*)pqkv;
    float* att = (float*)patt;
    float* zr  = (float*)pzr;
    float* wtq = (float*)pwq;
    float* wto = (float*)pwo;

    cudaFuncSetAttribute(tf32_gemm_pipe_kernel,
                         cudaFuncAttributeMaxDynamicSharedMemorySize, GEMM_SMEM);
    cudaFuncSetAttribute(flash_attn_tc2_kernel,
                         cudaFuncAttributeMaxDynamicSharedMemorySize, FLASH_SMEM);

    // 0) pre-round z; transpose+round weights
    {
        const int n4 = MROWS * DMODEL / 4;
        round_copy_kernel<<<(n4 + 255) / 256, 256>>>(
            (const float4*)z, (float4*)zr, n4);
    }
    transpose_round_kernel<<<dim3(QKVCOLS / 32, DMODEL / 32), dim3(32, 8)>>>(
        Wqkv, wtq, DMODEL, QKVCOLS);
    transpose_round_kernel<<<dim3(DMODEL / 32, DMODEL / 32), dim3(32, 8)>>>(
        Wout, wto, DMODEL, DMODEL);

    // 1) qkv = z @ Wqkv  (round output to tf32; pre-scale Q cols by QSCALE)
    tf32_gemm_pipe_kernel<<<dim3(QKVCOLS / 128, MROWS / 128), 256, GEMM_SMEM>>>(
        zr, wtq, qkv, MROWS, QKVCOLS, DMODEL, 1, DMODEL, QSCALE);

    // 2) causal flash attention (tensor cores, pipelined)
    flash_attn_tc2_kernel<<<dim3(TLEN / 128, NH, NB), 256, FLASH_SMEM>>>(qkv, att);

    // 3) out = att @ Wout  (plain fp32 output)
    tf32_gemm_pipe_kernel<<<dim3(DMODEL / 128, MROWS / 128), 256, GEMM_SMEM>>>(
        att, wto, out, MROWS, DMODEL, DMODEL, 0, 0, 1.0f);
}

// round 6
// speedup vs baseline: 4.0076x; 1.0499x over previous
#include <cuda_runtime.h>
#include <cstdint>
#include <cstddef>

// Problem constants
#define NB   4
#define TLEN 2048
#define DMODEL 1024
#define NH   16
#define DK   64
#define MROWS (NB * TLEN)        // 8192
#define QKVCOLS (3 * DMODEL)     // 3072

// Q pre-scale: 1/sqrt(64) * log2(e)  (softmax runs in exp2 domain)
#define QSCALE 0.1803368801111204f

// Scratch (device globals)
__device__ float g_qkv[(size_t)MROWS * QKVCOLS];        // 100.7 MB (tf32, Q pre-scaled)
__device__ float g_att[(size_t)MROWS * DMODEL];         // 33.6 MB  (tf32)
__device__ float g_zr[(size_t)MROWS * DMODEL];          // 33.6 MB  (z, tf32-rounded)
__device__ float g_vt[(size_t)NB * NH * DK * TLEN];     // 33.6 MB  (V^T per (n,h): [d][t])
__device__ float g_wtqkv[(size_t)QKVCOLS * DMODEL];     // 12.6 MB
__device__ float g_wtout[(size_t)DMODEL * DMODEL];      // 4.2 MB

__device__ __forceinline__ float tf32r(float x) {
    uint32_t u;
    asm("cvt.rna.tf32.f32 %0, %1;" : "=r"(u) : "f"(x));
    return __uint_as_float(u);
}

__device__ __forceinline__ float ex2(float x) {
    float y;
    asm("ex2.approx.f32 %0, %1;" : "=f"(y) : "f"(x));
    return y;
}

__device__ __forceinline__ uint32_t smem_u32(const void* p) {
    uint32_t a;
    asm("{ .reg .u64 t; cvta.to.shared.u64 t, %1; cvt.u32.u64 %0, t; }"
        : "=r"(a) : "l"(p));
    return a;
}

__device__ __forceinline__ void cp16(uint32_t dst, const void* src) {
    asm volatile("cp.async.cg.shared.global [%0], [%1], 16;"
                 :: "r"(dst), "l"(src));
}
#define CP_COMMIT() asm volatile("cp.async.commit_group;" ::: "memory")
#define CP_WAIT0()  asm volatile("cp.async.wait_group 0;" ::: "memory")

// ldmatrix x4 (bit-level 16B-row gather; valid for tf32 fragments)
__device__ __forceinline__ void ldsm_x4(uint32_t* r, uint32_t addr) {
    asm volatile("ldmatrix.sync.aligned.m8n8.x4.shared.b16 {%0,%1,%2,%3}, [%4];"
                 : "=r"(r[0]), "=r"(r[1]), "=r"(r[2]), "=r"(r[3]) : "r"(addr));
}

#define MMA_TF32(c, a, b)                                                     \
    asm volatile(                                                             \
        "mma.sync.aligned.m16n8k8.row.col.f32.tf32.tf32.f32 "                 \
        "{%0,%1,%2,%3}, {%4,%5,%6,%7}, {%8,%9}, {%0,%1,%2,%3};"               \
        : "+f"((c)[0]), "+f"((c)[1]), "+f"((c)[2]), "+f"((c)[3])              \
        : "r"((a)[0]), "r"((a)[1]), "r"((a)[2]), "r"((a)[3]),                 \
          "r"((b)[0]), "r"((b)[1]))

// ===========================================================================
// z -> tf32-rounded copy
// ===========================================================================
__global__ __launch_bounds__(256)
void round_copy_kernel(const float4* __restrict__ in, float4* __restrict__ out, int n4)
{
    int i = blockIdx.x * blockDim.x + threadIdx.x;
    if (i < n4) {
        float4 v = in[i];
        v.x = tf32r(v.x); v.y = tf32r(v.y);
        v.z = tf32r(v.z); v.w = tf32r(v.w);
        out[i] = v;
    }
}

// ===========================================================================
// Weight transpose + tf32 rounding
// ===========================================================================
__global__ __launch_bounds__(256)
void transpose_round_kernel(const float* __restrict__ W, float* __restrict__ WT,
                            int K, int N)
{
    __shared__ float tile[32][33];
    const int bx = blockIdx.x * 32;
    const int by = blockIdx.y * 32;
    const int tx = threadIdx.x;
    const int ty = threadIdx.y;
#pragma unroll
    for (int i = 0; i < 32; i += 8)
        tile[ty + i][tx] = W[(size_t)(by + ty + i) * N + bx + tx];
    __syncthreads();
#pragma unroll
    for (int i = 0; i < 32; i += 8)
        WT[(size_t)(bx + ty + i) * K + by + tx] = tf32r(tile[tx][ty + i]);
}

// ===========================================================================
// V transpose: vt[(n*16+h)*64 + d][t] = qkv[n*2048+t][2048 + h*64 + d]
// (values already tf32-rounded by GEMM1 epilogue)
// ===========================================================================
__global__ __launch_bounds__(256)
void vtrans_kernel(const float* __restrict__ qkv, float* __restrict__ vt)
{
    __shared__ float tile[32][33];
    const int nh = blockIdx.z;           // 0..63
    const int n = nh >> 4, h = nh & 15;
    const int t0 = blockIdx.x * 32;
    const int d0 = blockIdx.y * 32;
    const int tx = threadIdx.x;
    const int ty = threadIdx.y;
    const float* src = qkv + ((size_t)(n * TLEN + t0 + ty)) * QKVCOLS
                       + 2 * DMODEL + h * DK + d0 + tx;
#pragma unroll
    for (int i = 0; i < 32; i += 8)
        tile[ty + i][tx] = src[(size_t)i * QKVCOLS];
    __syncthreads();
    float* dst = vt + ((size_t)(nh * DK + d0 + ty)) * TLEN + t0 + tx;
#pragma unroll
    for (int i = 0; i < 32; i += 8)
        dst[(size_t)i * TLEN] = tile[tx][ty + i];
}

// ===========================================================================
// Pipelined tf32 GEMM with ldmatrix fragment loads.
// C[M,N] = A[M,K] * BT[N,K]^T; CTA 128x128, BK=32, 8 warps (2Mx4N).
// ===========================================================================
#define SSTRIDE 36
#define GEMM_SMEM (4 * 128 * SSTRIDE * 4)   // 2 bufs x (sA+sB)

__global__ __launch_bounds__(256, 2)
void tf32_gemm_pipe_kernel(const float* __restrict__ A, const float* __restrict__ BT,
                           float* __restrict__ C, int M, int N, int K,
                           int roundOut, int qlimit, float qscale)
{
    extern __shared__ float gs[];
    float* sA = gs;
    float* sB = gs + 2 * 128 * SSTRIDE;

    const int tid = threadIdx.x;
    const int wid = tid >> 5;
    const int lane = tid & 31;
    const int row0 = blockIdx.y * 128;
    const int col0 = blockIdx.x * 128;

    const int warpM = wid >> 2;
    const int warpN = wid & 3;
    const int qrow = lane >> 2;
    const int qk   = lane & 3;

    // ldmatrix per-thread address components
    const int lm_row = lane & 7;
    const int lm_mat = lane >> 3;
    const int rowA_off = lm_row + ((lm_mat & 1) << 3);   // row within 16
    const int colA_off = (lm_mat >> 1) << 2;             // 0 or 4
    const int rowB_off = lm_row;                         // row within 8
    const int colB_off = lm_mat << 2;                    // 0,4,8,12

    const int skq  = (tid & 7) << 2;
    const int srow = tid >> 3;

    const float* Abase = A  + (size_t)(row0 + srow) * K + skq;
    const float* Bbase = BT + (size_t)(col0 + srow) * K + skq;

    const uint32_t sA_u32 = smem_u32(sA);
    const uint32_t sB_u32 = smem_u32(sB);
    const uint32_t dA0 = sA_u32 + (uint32_t)(srow * SSTRIDE + skq) * 4u;
    const uint32_t dB0 = sB_u32 + (uint32_t)(srow * SSTRIDE + skq) * 4u;
    const uint32_t BUFB = 128u * SSTRIDE * 4u;

    // ldmatrix base offsets (bytes), before buffer/mt/nt/k offsets
    const uint32_t aLm0 = sA_u32 +
        (uint32_t)((warpM * 64 + rowA_off) * SSTRIDE + colA_off) * 4u;
    const uint32_t bLm0 = sB_u32 +
        (uint32_t)((warpN * 32 + rowB_off) * SSTRIDE + colB_off) * 4u;

    float c[4][4][4];
#pragma unroll
    for (int mt = 0; mt < 4; mt++)
#pragma unroll
        for (int nt = 0; nt < 4; nt++)
#pragma unroll
            for (int r = 0; r < 4; r++) c[mt][nt][r] = 0.0f;

    // prologue: prefetch chunk 0 into buffer 0
#pragma unroll
    for (int i = 0; i < 4; i++) {
        cp16(dA0 + (uint32_t)(i * 32 * SSTRIDE) * 4u, Abase + (size_t)(i * 32) * K);
        cp16(dB0 + (uint32_t)(i * 32 * SSTRIDE) * 4u, Bbase + (size_t)(i * 32) * K);
    }
    CP_COMMIT();

    const int niter = K >> 5;
    for (int it = 0; it < niter; it++) {
        CP_WAIT0();
        __syncthreads();
        if (it + 1 < niter) {
            const int k0 = (it + 1) << 5;
            const uint32_t bo = ((it + 1) & 1) * BUFB;
#pragma unroll
            for (int i = 0; i < 4; i++) {
                cp16(dA0 + bo + (uint32_t)(i * 32 * SSTRIDE) * 4u,
                     Abase + (size_t)(i * 32) * K + k0);
                cp16(dB0 + bo + (uint32_t)(i * 32 * SSTRIDE) * 4u,
                     Bbase + (size_t)(i * 32) * K + k0);
            }
            CP_COMMIT();
        }

        const uint32_t bo = (it & 1) * BUFB;
        const uint32_t aB = aLm0 + bo;
        const uint32_t bB = bLm0 + bo;

#pragma unroll
        for (int kh = 0; kh < 2; kh++) {        // 16-wide halves
            uint32_t bfr[4][4];
#pragma unroll
            for (int nt = 0; nt < 4; nt++)
                ldsm_x4(bfr[nt], bB + (uint32_t)(nt * 8 * SSTRIDE + kh * 16) * 4u);
#pragma unroll
            for (int ks = 0; ks < 2; ks++) {    // k-steps of 8
                const uint32_t kk = (uint32_t)(kh * 16 + ks * 8);
                uint32_t afr[4][4];
#pragma unroll
                for (int mt = 0; mt < 4; mt++)
                    ldsm_x4(afr[mt], aB + (uint32_t)(mt * 16 * SSTRIDE + kk) * 4u);
#pragma unroll
                for (int mt = 0; mt < 4; mt++)
#pragma unroll
                    for (int nt = 0; nt < 4; nt++)
                        MMA_TF32(c[mt][nt], afr[mt], &bfr[nt][2 * ks]);
            }
        }
    }

    const float fac = (col0 < qlimit) ? qscale : 1.0f;
#pragma unroll
    for (int mt = 0; mt < 4; mt++) {
        const int r = row0 + warpM * 64 + mt * 16 + qrow;
#pragma unroll
        for (int nt = 0; nt < 4; nt++) {
            const int col = col0 + warpN * 32 + nt * 8 + qk * 2;
            float2 v0, v1;
            if (roundOut) {
                v0 = make_float2(tf32r(c[mt][nt][0] * fac), tf32r(c[mt][nt][1] * fac));
                v1 = make_float2(tf32r(c[mt][nt][2] * fac), tf32r(c[mt][nt][3] * fac));
            } else {
                v0 = make_float2(c[mt][nt][0], c[mt][nt][1]);
                v1 = make_float2(c[mt][nt][2], c[mt][nt][3]);
            }
            *reinterpret_cast<float2*>(C + (size_t)r * N + col) = v0;
            *reinterpret_cast<float2*>(C + (size_t)(r + 8) * N + col) = v1;
        }
    }
}

// ===========================================================================
// Tensor-core causal flash attention: ldmatrix fragments for K, P, V^T.
// CTA: 128 q-rows; 8 warps, 16 q-rows each. exp2-domain softmax.
// ===========================================================================
#define KSTR 68
#define VSTR 68
#define PSTR 68
#define KBUF (64 * KSTR)
#define VBUF (64 * VSTR)
#define FLASH_SMEM ((2 * KBUF + 2 * VBUF + 128 * PSTR) * 4)

__global__ __launch_bounds__(256, 2)
void flash_attn_tc3_kernel(const float* __restrict__ qkv, const float* __restrict__ vt,
                           float* __restrict__ attout)
{
    extern __shared__ float smem[];
    float* sK = smem;                        // [2][64][KSTR], rows = key t
    float* sVT = smem + 2 * KBUF;            // [2][64][VSTR], rows = d
    float* sP = smem + 2 * KBUF + 2 * VBUF;  // [128][PSTR]

    const int qb = (int)gridDim.x - 1 - (int)blockIdx.x;
    const int h = blockIdx.y;
    const int n = blockIdx.z;
    const int tid = threadIdx.x;
    const int wid = tid >> 5;
    const int lane = tid & 31;
    const int qrow = lane >> 2;
    const int qk = lane & 3;
    const int q0 = qb * 128;

    const int lm_row = lane & 7;
    const int lm_mat = lane >> 3;
    const int rowA_off = lm_row + ((lm_mat & 1) << 3);
    const int colA_off = (lm_mat >> 1) << 2;
    const int rowB_off = lm_row;
    const int colB_off = lm_mat << 2;

    const size_t rs = QKVCOLS;
    const int ntiles = 2 * qb + 2;

    const int c4 = (tid & 15) << 2;
    const int r0 = tid >> 4;

    const float* kg0 = qkv + ((size_t)(n * TLEN) + r0) * rs + DMODEL + h * DK + c4;
    const float* vg0 = vt + ((size_t)((n * NH + h) * DK + r0)) * TLEN + c4;
    const uint32_t sK_u32 = smem_u32(sK);
    const uint32_t sVT_u32 = smem_u32(sVT);
    const uint32_t sP_u32 = smem_u32(sP);
    const uint32_t dK0 = sK_u32 + (uint32_t)(r0 * KSTR + c4) * 4u;
    const uint32_t dV0 = sVT_u32 + (uint32_t)(r0 * VSTR + c4) * 4u;

    // prefetch K/V^T tile 0
    {
#pragma unroll
        for (int r = 0; r < 4; r++) {
            cp16(dK0 + (uint32_t)(16 * r * KSTR) * 4u, kg0 + (size_t)(16 * r) * rs);
            cp16(dV0 + (uint32_t)(16 * r * VSTR) * 4u, vg0 + (size_t)(16 * r) * TLEN);
        }
        CP_COMMIT();
    }

    // stage Q (pre-scaled tf32)
    {
        const float* qg = qkv + ((size_t)(n * TLEN + q0 + r0)) * rs + h * DK + c4;
        float* ps = sP + r0 * PSTR + c4;
#pragma unroll
        for (int r = 0; r < 8; r++)
            *reinterpret_cast<float4*>(ps + 16 * r * PSTR) =
                *reinterpret_cast<const float4*>(qg + (size_t)(16 * r) * rs);
    }
    __syncthreads();

    // Q fragments via ldmatrix (warp-private rows)
    uint32_t qf[8][4];
    {
        const uint32_t qLm = sP_u32 +
            (uint32_t)((wid * 16 + rowA_off) * PSTR + colA_off) * 4u;
#pragma unroll
        for (int kc = 0; kc < 8; kc++)
            ldsm_x4(qf[kc], qLm + (uint32_t)(kc * 8) * 4u);
    }

    float o[8][4];
#pragma unroll
    for (int nt = 0; nt < 8; nt++)
#pragma unroll
        for (int r = 0; r < 4; r++) o[nt][r] = 0.0f;

    float m0 = -1e30f, m1 = -1e30f, l0 = 0.0f, l1 = 0.0f;

    const int q_abs0 = q0 + wid * 16 + qrow;
    const int q_abs1 = q_abs0 + 8;
    const int wmax_kt = (q0 + wid * 16 + 15) >> 6;

    const uint32_t kLm0 = sK_u32 + (uint32_t)(rowB_off * KSTR + colB_off) * 4u;
    const uint32_t vLm0 = sVT_u32 + (uint32_t)(rowB_off * VSTR + colB_off) * 4u;
    const uint32_t pLm0 = sP_u32 +
        (uint32_t)((wid * 16 + rowA_off) * PSTR + colA_off) * 4u;

    for (int kt = 0; kt < ntiles; kt++) {
        CP_WAIT0();
        __syncthreads();

        if (kt + 1 < ntiles) {
            const uint32_t bK = ((kt + 1) & 1) * (uint32_t)(KBUF * 4);
            const uint32_t bV = ((kt + 1) & 1) * (uint32_t)(VBUF * 4);
            const float* kg = kg0 + (size_t)((kt + 1) * 64) * rs;
            const float* vg = vg0 + (kt + 1) * 64;
#pragma unroll
            for (int r = 0; r < 4; r++) {
                cp16(dK0 + bK + (uint32_t)(16 * r * KSTR) * 4u, kg + (size_t)(16 * r) * rs);
                cp16(dV0 + bV + (uint32_t)(16 * r * VSTR) * 4u, vg + (size_t)(16 * r) * TLEN);
            }
            CP_COMMIT();
        }

        if (kt > wmax_kt) continue;

        const uint32_t kB = kLm0 + (kt & 1) * (uint32_t)(KBUF * 4);
        const uint32_t vB = vLm0 + (kt & 1) * (uint32_t)(VBUF * 4);

        // ---- S = Q K^T ----
        float s[8][4];
#pragma unroll
        for (int nt = 0; nt < 8; nt++)
#pragma unroll
            for (int r = 0; r < 4; r++) s[nt][r] = 0.0f;

#pragma unroll
        for (int kcp = 0; kcp < 4; kcp++) {     // pairs of k-steps (d dim)
#pragma unroll
            for (int nt = 0; nt < 8; nt++) {
                uint32_t bk[4];
                ldsm_x4(bk, kB + (uint32_t)(nt * 8 * KSTR + kcp * 16) * 4u);
                MMA_TF32(s[nt], qf[2 * kcp], &bk[0]);
                MMA_TF32(s[nt], qf[2 * kcp + 1], &bk[2]);
            }
        }

        // ---- causal mask ----
        if (((kt << 6) + 63) > (q0 + wid * 16)) {
#pragma unroll
            for (int nt = 0; nt < 8; nt++) {
                const int c0 = (kt << 6) + (nt << 3) + (qk << 1);
                if (c0     > q_abs0) s[nt][0] = -1e30f;
                if (c0 + 1 > q_abs0) s[nt][1] = -1e30f;
                if (c0     > q_abs1) s[nt][2] = -1e30f;
                if (c0 + 1 > q_abs1) s[nt][3] = -1e30f;
            }
        }

        // ---- online softmax (exp2 domain) ----
        float rm0 = -1e30f, rm1 = -1e30f;
#pragma unroll
        for (int nt = 0; nt < 8; nt++) {
            rm0 = fmaxf(rm0, fmaxf(s[nt][0], s[nt][1]));
            rm1 = fmaxf(rm1, fmaxf(s[nt][2], s[nt][3]));
        }
        rm0 = fmaxf(rm0, __shfl_xor_sync(0xffffffffu, rm0, 1));
        rm0 = fmaxf(rm0, __shfl_xor_sync(0xffffffffu, rm0, 2));
        rm1 = fmaxf(rm1, __shfl_xor_sync(0xffffffffu, rm1, 1));
        rm1 = fmaxf(rm1, __shfl_xor_sync(0xffffffffu, rm1, 2));

        const float mn0 = fmaxf(m0, rm0);
        const float mn1 = fmaxf(m1, rm1);
        const float corr0 = ex2(m0 - mn0);
        const float corr1 = ex2(m1 - mn1);
        m0 = mn0; m1 = mn1;

        float rs0 = 0.0f, rs1 = 0.0f;
#pragma unroll
        for (int nt = 0; nt < 8; nt++) {
            s[nt][0] = ex2(s[nt][0] - mn0);
            s[nt][1] = ex2(s[nt][1] - mn0);
            s[nt][2] = ex2(s[nt][2] - mn1);
            s[nt][3] = ex2(s[nt][3] - mn1);
            rs0 += s[nt][0] + s[nt][1];
            rs1 += s[nt][2] + s[nt][3];
        }
        rs0 += __shfl_xor_sync(0xffffffffu, rs0, 1);
        rs0 += __shfl_xor_sync(0xffffffffu, rs0, 2);
        rs1 += __shfl_xor_sync(0xffffffffu, rs1, 1);
        rs1 += __shfl_xor_sync(0xffffffffu, rs1, 2);

        l0 = l0 * corr0 + rs0;
        l1 = l1 * corr1 + rs1;

#pragma unroll
        for (int nt = 0; nt < 8; nt++) {
            o[nt][0] *= corr0; o[nt][1] *= corr0;
            o[nt][2] *= corr1; o[nt][3] *= corr1;
        }

        // ---- P -> smem (warp-private rows), tf32-rounded ----
        {
            float* pw = sP + (wid * 16 + qrow) * PSTR + (qk << 1);
#pragma unroll
            for (int nt = 0; nt < 8; nt++) {
                *reinterpret_cast<float2*>(pw + nt * 8) =
                    make_float2(tf32r(s[nt][0]), tf32r(s[nt][1]));
                *reinterpret_cast<float2*>(pw + 8 * PSTR + nt * 8) =
                    make_float2(tf32r(s[nt][2]), tf32r(s[nt][3]));
            }
        }
        __syncwarp();

        // ---- O += P V  (P via ldmatrix A-frags, V^T via ldmatrix B-frags) ----
#pragma unroll
        for (int kvp = 0; kvp < 4; kvp++) {     // pairs of kv k-steps
            uint32_t af0[4], af1[4];
            ldsm_x4(af0, pLm0 + (uint32_t)(kvp * 16) * 4u);
            ldsm_x4(af1, pLm0 + (uint32_t)(kvp * 16 + 8) * 4u);
#pragma unroll
            for (int nt = 0; nt < 8; nt++) {
                uint32_t bv[4];
                ldsm_x4(bv, vB + (uint32_t)(nt * 8 * VSTR + kvp * 16) * 4u);
                MMA_TF32(o[nt], af0, &bv[0]);
                MMA_TF32(o[nt], af1, &bv[2]);
            }
        }
        __syncwarp();
    }

    // ---- epilogue ----
    const float inv0 = 1.0f / l0;
    const float inv1 = 1.0f / l1;
    float* ob = attout + ((size_t)(n * TLEN + q0 + wid * 16 + qrow)) * DMODEL
                + h * DK + (qk << 1);
#pragma unroll
    for (int nt = 0; nt < 8; nt++) {
        *reinterpret_cast<float2*>(ob + nt * 8) =
            make_float2(tf32r(o[nt][0] * inv0), tf32r(o[nt][1] * inv0));
        *reinterpret_cast<float2*>(ob + (size_t)8 * DMODEL + nt * 8) =
            make_float2(tf32r(o[nt][2] * inv1), tf32r(o[nt][3] * inv1));
    }
}

// ---------------------------------------------------------------------------
// Launch
// ---------------------------------------------------------------------------
extern "C" void kernel_launch(void* const* d_in, const int* in_sizes, int n_in,
                              void* d_out, int out_size)
{
    const float* z    = (const float*)d_in[0];
    const float* Wqkv = (const float*)d_in[1];
    const float* Wout = (const float*)d_in[2];
    float* out = (float*)d_out;

    void *pqkv, *patt, *pzr, *pvt, *pwq, *pwo;
    cudaGetSymbolAddress(&pqkv, g_qkv);
    cudaGetSymbolAddress(&patt, g_att);
    cudaGetSymbolAddress(&pzr, g_zr);
    cudaGetSymbolAddress(&pvt, g_vt);
    cudaGetSymbolAddress(&pwq, g_wtqkv);
    cudaGetSymbolAddress(&pwo, g_wtout);
    float* qkv = (float*)pqkv;
    float* att = (float*)patt;
    float* zr  = (float*)pzr;
    float* vt  = (float*)pvt;
    float* wtq = (float*)pwq;
    float* wto = (float*)pwo;

    cudaFuncSetAttribute(tf32_gemm_pipe_kernel,
                         cudaFuncAttributeMaxDynamicSharedMemorySize, GEMM_SMEM);
    cudaFuncSetAttribute(flash_attn_tc3_kernel,
                         cudaFuncAttributeMaxDynamicSharedMemorySize, FLASH_SMEM);

    // 0) pre-round z; transpose+round weights
    {
        const int n4 = MROWS * DMODEL / 4;
        round_copy_kernel<<<(n4 + 255) / 256, 256>>>(
            (const float4*)z, (float4*)zr, n4);
    }
    transpose_round_kernel<<<dim3(QKVCOLS / 32, DMODEL / 32), dim3(32, 8)>>>(
        Wqkv, wtq, DMODEL, QKVCOLS);
    transpose_round_kernel<<<dim3(DMODEL / 32, DMODEL / 32), dim3(32, 8)>>>(
        Wout, wto, DMODEL, DMODEL);

    // 1) qkv = z @ Wqkv  (tf32 out; Q cols pre-scaled by QSCALE)
    tf32_gemm_pipe_kernel<<<dim3(QKVCOLS / 128, MROWS / 128), 256, GEMM_SMEM>>>(
        zr, wtq, qkv, MROWS, QKVCOLS, DMODEL, 1, DMODEL, QSCALE);

    // 1b) V^T per (n,h)
    vtrans_kernel<<<dim3(TLEN / 32, DK / 32, NB * NH), dim3(32, 8)>>>(qkv, vt);

    // 2) causal flash attention
    flash_attn_tc3_kernel<<<dim3(TLEN / 128, NH, NB), 256, FLASH_SMEM>>>(qkv, vt, att);

    // 3) out = att @ Wout
    tf32_gemm_pipe_kernel<<<dim3(DMODEL / 128, MROWS / 128), 256, GEMM_SMEM>>>(
        att, wto, out, MROWS, DMODEL, DMODEL, 0, 0, 1.0f);
}